// round 5
// baseline (speedup 1.0000x reference)
#include <cuda_runtime.h>
#include <math.h>

typedef unsigned long long ull;

#define DINL __device__ __forceinline__

DINL ull pk2(float lo, float hi) {
    ull r; asm("mov.b64 %0, {%1,%2};" : "=l"(r) : "f"(lo), "f"(hi)); return r;
}
DINL void upk2(ull v, float& lo, float& hi) {
    asm("mov.b64 {%0,%1}, %2;" : "=f"(lo), "=f"(hi) : "l"(v));
}
DINL ull ffma2(ull a, ull b, ull c) {
    ull d; asm("fma.rn.f32x2 %0, %1, %2, %3;" : "=l"(d) : "l"(a), "l"(b), "l"(c)); return d;
}
DINL float ex2f(float x) {
    float y; asm("ex2.approx.f32 %0, %1;" : "=f"(y) : "f"(x)); return y;
}
DINL float gelu_exact(float x) {
    return 0.5f * x * (1.0f + erff(x * 0.7071067811865476f));
}

constexpr int B  = 2;
constexpr int C  = 64;
constexpr int HW = 48;
constexpr int N  = 2304;   // 48*48
constexpr int H  = 8;      // heads
constexpr int D  = 8;      // head dim
constexpr int KS = 8;      // key split
constexpr int KQ2 = N / KS; // 288 keys per slice

constexpr float QS     = 0.3535533905932738f * 1.4426950408889634f; // scale * log2(e)
constexpr float SHIFTF = -14.4269504088896f;                         // cancels in normalization

// ---------------- scratch (device globals; no allocs allowed) ----------------
__device__ __align__(16) float g_qkv[2][3][B * H * N * D];    // [stream][q,k,v] (b,h,n,d)
__device__ __align__(16) float g_pacc[4 * KS * N * C];        // [z][slice][n][c] unnormalized P·V
__device__ __align__(16) float g_psum[4 * KS * H * N];        // [z][slice][h][n]  sum of p
__device__ __align__(16) float g_wefft[2][C * C];             // effective weights, [att][k*64+o]
__device__ __align__(16) float g_beff[C];                     // effective bias

// ---------------- kernel 1: fused QKV GEMMs (both streams; depth path inlined) ----------------
__global__ void k_qkv(const float* __restrict__ rgb,
                      const float* __restrict__ depth,
                      const float* __restrict__ w_exp,
                      const float* __restrict__ b_exp,
                      const float* __restrict__ wq0, const float* __restrict__ wk0, const float* __restrict__ wv0,
                      const float* __restrict__ wq1, const float* __restrict__ wk1, const float* __restrict__ wv1) {
    extern __shared__ float sm[];
    float* sX  = sm;                 // [c][h] stride 49
    float* sWt = sm + 64 * 49;       // [c][oc] stride 196

    int w = blockIdx.x, b = blockIdx.y, s = blockIdx.z;
    int tid = threadIdx.x;           // 288 threads

    if (s == 0) {
        for (int idx = tid; idx < 64 * 48; idx += 288) {
            int c = idx / 48, h = idx % 48;
            sX[c * 49 + h] = rgb[(b * C + c) * N + h * HW + w];
        }
    } else {
        float sx = w * 0.5f - 0.25f;
        float fx = floorf(sx);
        float wx1 = sx - fx, wx0 = 1.0f - wx1;
        int x0 = max((int)fx, 0), x1 = min((int)fx + 1, 23);
        const float* dp = depth + b * 576;
        for (int idx = tid; idx < 64 * 48; idx += 288) {
            int c = idx / 48, h = idx % 48;
            float sy = h * 0.5f - 0.25f;
            float fy = floorf(sy);
            float wy1 = sy - fy, wy0 = 1.0f - wy1;
            int y0 = max((int)fy, 0), y1 = min((int)fy + 1, 23);
            float d00 = dp[y0 * 24 + x0], d01 = dp[y0 * 24 + x1];
            float d10 = dp[y1 * 24 + x0], d11 = dp[y1 * 24 + x1];
            float we = w_exp[c], be = b_exp[c];
            float v = wy0 * wx0 * fmaxf(fmaf(we, d00, be), 0.f)
                    + wy0 * wx1 * fmaxf(fmaf(we, d01, be), 0.f)
                    + wy1 * wx0 * fmaxf(fmaf(we, d10, be), 0.f)
                    + wy1 * wx1 * fmaxf(fmaf(we, d11, be), 0.f);
            sX[c * 49 + h] = v;
        }
    }
    const float* wq = s ? wq1 : wq0;
    const float* wk = s ? wk1 : wk0;
    const float* wv = s ? wv1 : wv0;
    for (int idx = tid; idx < 64 * 192; idx += 288) {
        int oc = idx / 64, c = idx % 64;
        int sel = oc >> 6, ocm = oc & 63;
        const float* wm = (sel == 0) ? wq : (sel == 1 ? wk : wv);
        sWt[c * 196 + oc] = wm[ocm * 64 + c];
    }
    __syncthreads();

    int nl = tid % 48;        // = h
    int g  = tid / 48;        // 0..5
    int oc0 = g * 32;

    ull acc[16];
#pragma unroll
    for (int j = 0; j < 16; j++) acc[j] = 0ull;

    for (int c = 0; c < 64; c++) {
        float xv = sX[c * 49 + nl];
        ull xp = pk2(xv, xv);
        const ulonglong2* w2 = (const ulonglong2*)(sWt + c * 196 + oc0);
#pragma unroll
        for (int j = 0; j < 8; j++) {
            ulonglong2 wv2 = w2[j];
            acc[2 * j]     = ffma2(xp, wv2.x, acc[2 * j]);
            acc[2 * j + 1] = ffma2(xp, wv2.y, acc[2 * j + 1]);
        }
    }

    int n = w * HW + nl;
#pragma unroll
    for (int j = 0; j < 16; j++) {
        int oc = oc0 + 2 * j;
        int mat = oc >> 6, ocm = oc & 63, hd = ocm >> 3, d = ocm & 7;
        float lo, hi; upk2(acc[j], lo, hi);
        *(float2*)&g_qkv[s][mat][((size_t)(b * H + hd) * N + n) * D + d] = make_float2(lo, hi);
    }
}

// ---------------- kernel 2: cross-attention v6 ----------------
// key-split 8 (288 keys/slice), K and V duplicated-pair in smem (36.9KB).
// 128-thread CTAs, 4 queries/thread via 2 query-pair packs.
// grid: x = q-chunk (5: 4 full 512q + 1 tail 256q), y = h + 8*slice (64), z = att*2+b (4).
template<bool FULLB>
DINL void attn_core(const ulonglong2* __restrict__ sK2, const ulonglong2* __restrict__ sV2,
                    const ull* qA, const ull* qB,
                    ull* accA, ull* accB, ull& ssA, ull& ssB) {
    const ull SH2  = pk2(SHIFTF, SHIFTF);
    const ull ONE2 = pk2(1.0f, 1.0f);
#pragma unroll 2
    for (int key = 0; key < KQ2; key++) {
        ulonglong2 k0 = sK2[4 * key],     k1 = sK2[4 * key + 1];
        ulonglong2 k2 = sK2[4 * key + 2], k3 = sK2[4 * key + 3];
        ull tA = ffma2(qA[0], k0.x, SH2);
        ull tB;
        if (FULLB) tB = ffma2(qB[0], k0.x, SH2);
        tA = ffma2(qA[1], k0.y, tA); if (FULLB) tB = ffma2(qB[1], k0.y, tB);
        tA = ffma2(qA[2], k1.x, tA); if (FULLB) tB = ffma2(qB[2], k1.x, tB);
        tA = ffma2(qA[3], k1.y, tA); if (FULLB) tB = ffma2(qB[3], k1.y, tB);
        tA = ffma2(qA[4], k2.x, tA); if (FULLB) tB = ffma2(qB[4], k2.x, tB);
        tA = ffma2(qA[5], k2.y, tA); if (FULLB) tB = ffma2(qB[5], k2.y, tB);
        tA = ffma2(qA[6], k3.x, tA); if (FULLB) tB = ffma2(qB[6], k3.x, tB);
        tA = ffma2(qA[7], k3.y, tA); if (FULLB) tB = ffma2(qB[7], k3.y, tB);

        float a0, a1; upk2(tA, a0, a1);
        ull ppA = pk2(ex2f(a0), ex2f(a1));
        ssA = ffma2(ppA, ONE2, ssA);
        ull ppB;
        if (FULLB) {
            float b0, b1; upk2(tB, b0, b1);
            ppB = pk2(ex2f(b0), ex2f(b1));
            ssB = ffma2(ppB, ONE2, ssB);
        }

        ulonglong2 v0 = sV2[4 * key],     v1 = sV2[4 * key + 1];
        ulonglong2 v2 = sV2[4 * key + 2], v3 = sV2[4 * key + 3];
        accA[0] = ffma2(ppA, v0.x, accA[0]); accA[1] = ffma2(ppA, v0.y, accA[1]);
        accA[2] = ffma2(ppA, v1.x, accA[2]); accA[3] = ffma2(ppA, v1.y, accA[3]);
        accA[4] = ffma2(ppA, v2.x, accA[4]); accA[5] = ffma2(ppA, v2.y, accA[5]);
        accA[6] = ffma2(ppA, v3.x, accA[6]); accA[7] = ffma2(ppA, v3.y, accA[7]);
        if (FULLB) {
            accB[0] = ffma2(ppB, v0.x, accB[0]); accB[1] = ffma2(ppB, v0.y, accB[1]);
            accB[2] = ffma2(ppB, v1.x, accB[2]); accB[3] = ffma2(ppB, v1.y, accB[3]);
            accB[4] = ffma2(ppB, v2.x, accB[4]); accB[5] = ffma2(ppB, v2.y, accB[5]);
            accB[6] = ffma2(ppB, v3.x, accB[6]); accB[7] = ffma2(ppB, v3.y, accB[7]);
        }
    }
}

DINL void load_qpack(const float* __restrict__ Qb, int n0, int n1, ull* qp) {
    float4 a = *(const float4*)(Qb + (size_t)n0 * D);
    float4 b = *(const float4*)(Qb + (size_t)n0 * D + 4);
    float4 c = *(const float4*)(Qb + (size_t)n1 * D);
    float4 d = *(const float4*)(Qb + (size_t)n1 * D + 4);
    qp[0] = pk2(a.x * QS, c.x * QS); qp[1] = pk2(a.y * QS, c.y * QS);
    qp[2] = pk2(a.z * QS, c.z * QS); qp[3] = pk2(a.w * QS, c.w * QS);
    qp[4] = pk2(b.x * QS, d.x * QS); qp[5] = pk2(b.y * QS, d.y * QS);
    qp[6] = pk2(b.z * QS, d.z * QS); qp[7] = pk2(b.w * QS, d.w * QS);
}

DINL void store_pack(const ull* acc, ull ss, int zslice, int h, int n0, int n1) {
    float o0[8], o1[8];
#pragma unroll
    for (int d = 0; d < 8; d++) upk2(acc[d], o0[d], o1[d]);
    size_t pb0 = ((size_t)zslice * N + n0) * C + h * D;
    size_t pb1 = ((size_t)zslice * N + n1) * C + h * D;
    *(float4*)&g_pacc[pb0]     = make_float4(o0[0], o0[1], o0[2], o0[3]);
    *(float4*)&g_pacc[pb0 + 4] = make_float4(o0[4], o0[5], o0[6], o0[7]);
    *(float4*)&g_pacc[pb1]     = make_float4(o1[0], o1[1], o1[2], o1[3]);
    *(float4*)&g_pacc[pb1 + 4] = make_float4(o1[4], o1[5], o1[6], o1[7]);
    float s0, s1; upk2(ss, s0, s1);
    size_t sb = ((size_t)zslice * H + h) * N;
    g_psum[sb + n0] = s0;
    g_psum[sb + n1] = s1;
}

__global__ void __launch_bounds__(128, 4) k_attn() {
    extern __shared__ float sm[];
    ull* sKd = (ull*)sm;               // [288][8] (k,k) pairs = 18432 B
    ull* sVd = sKd + KQ2 * 8;          // [288][8] (v,v) pairs = 18432 B

    int chunk = blockIdx.x;            // 0..4
    int h = blockIdx.y & 7, slice = blockIdx.y >> 3;
    int z = blockIdx.z;                // att*2+b
    int att = z >> 1, b = z & 1;
    int tid = threadIdx.x;

    const float4* Kg4 = (const float4*)(g_qkv[1 - att][1] + ((size_t)(b * H + h) * N + slice * KQ2) * D);
    const float4* Vg4 = (const float4*)(g_qkv[1 - att][2] + ((size_t)(b * H + h) * N + slice * KQ2) * D);

    for (int j = tid; j < KQ2; j += 128) {
        float4 k0 = Kg4[2 * j], k1 = Kg4[2 * j + 1];
        ull* dk = sKd + j * 8;
        dk[0] = pk2(k0.x, k0.x); dk[1] = pk2(k0.y, k0.y);
        dk[2] = pk2(k0.z, k0.z); dk[3] = pk2(k0.w, k0.w);
        dk[4] = pk2(k1.x, k1.x); dk[5] = pk2(k1.y, k1.y);
        dk[6] = pk2(k1.z, k1.z); dk[7] = pk2(k1.w, k1.w);
        float4 v0 = Vg4[2 * j], v1 = Vg4[2 * j + 1];
        ull* dv = sVd + j * 8;
        dv[0] = pk2(v0.x, v0.x); dv[1] = pk2(v0.y, v0.y);
        dv[2] = pk2(v0.z, v0.z); dv[3] = pk2(v0.w, v0.w);
        dv[4] = pk2(v1.x, v1.x); dv[5] = pk2(v1.y, v1.y);
        dv[6] = pk2(v1.z, v1.z); dv[7] = pk2(v1.w, v1.w);
    }
    __syncthreads();

    const float* Qb = g_qkv[att][0] + (size_t)(b * H + h) * N * D;
    int base = chunk * 512;
    int n0 = base + tid, n1 = n0 + 128;          // pack A
    int n2 = n0 + 256,   n3 = n0 + 384;          // pack B (full chunks only)
    bool fullB = (chunk < 4);

    ull qA[8], qB[8];
    load_qpack(Qb, n0, n1, qA);
    if (fullB) load_qpack(Qb, n2, n3, qB);

    const ulonglong2* sK2 = (const ulonglong2*)sKd;
    const ulonglong2* sV2 = (const ulonglong2*)sVd;

    ull accA[8], accB[8];
#pragma unroll
    for (int d = 0; d < 8; d++) { accA[d] = 0ull; accB[d] = 0ull; }
    ull ssA = 0ull, ssB = 0ull;

    if (fullB) attn_core<true >(sK2, sV2, qA, qB, accA, accB, ssA, ssB);
    else       attn_core<false>(sK2, sV2, qA, qB, accA, accB, ssA, ssB);

    int zslice = z * KS + slice;
    store_pack(accA, ssA, zslice, h, n0, n1);
    if (fullB) store_pack(accB, ssB, zslice, h, n2, n3);
}

// ---------------- kernel 3: effective proj+compress weights ----------------
__global__ void k_weff(const float* __restrict__ wrp, const float* __restrict__ brp,
                       const float* __restrict__ wdp, const float* __restrict__ bdp,
                       const float* __restrict__ wcomp, const float* __restrict__ bcomp) {
    __shared__ float sWc[128];
    __shared__ float sRed[64];
    int o = blockIdx.x;
    int tid = threadIdx.x;   // 128
    sWc[tid] = wcomp[o * 128 + tid];
    __syncthreads();
    int att = tid >> 6, k = tid & 63;
    const float* wp = att ? wdp : wrp;
    float acc = 0.f;
#pragma unroll
    for (int c = 0; c < 64; c++)
        acc = fmaf(sWc[att * 64 + c], wp[c * 64 + k], acc);
    g_wefft[att][k * 64 + o] = acc;
    if (tid < 64) sRed[tid] = sWc[tid] * brp[tid] + sWc[64 + tid] * bdp[tid];
    __syncthreads();
    if (tid == 0) {
        float a = bcomp[o];
        for (int c = 0; c < 64; c++) a += sRed[c];
        g_beff[o] = a;
    }
}

// ---------------- kernel 4: combine partials + (proj+compress) GEMM + GELU ----------------
// 288 blocks x 16 rows, 256 threads
__global__ void k_out(float* __restrict__ out) {
    extern __shared__ float sm[];
    float* sA   = sm;            // [att][r][k] stride 65 -> 2080 floats
    float* sW   = sm + 2080;     // [att][k][o]          -> 8192 floats
    float* sInv = sm + 10272;    // [att][r][h]          -> 256 floats
    float* sB   = sm + 10528;    // 64 floats

    int tid = threadIdx.x;
    int row0 = blockIdx.x * 16;
    int bb = row0 / N;
    int nb = row0 - bb * N;

    // 1/(sum over KS slices of psum)
    if (tid < 256) {
        int idx = tid;
        int att = idx >> 7, r = (idx >> 3) & 15, hh = idx & 7;
        int n = nb + r;
        int z = att * 2 + bb;
        float s = 0.f;
#pragma unroll
        for (int qq = 0; qq < KS; qq++)
            s += g_psum[(((size_t)z * KS + qq) * H + hh) * N + n];
        sInv[(att * 16 + r) * 8 + hh] = 1.0f / s;
    }
    for (int idx = tid; idx < 2 * 64 * 64; idx += 256)
        sW[idx] = ((const float*)g_wefft)[idx];
    if (tid < 64) sB[tid] = g_beff[tid];
    __syncthreads();

    // combine pacc slices, normalize -> sA
    for (int idx = tid; idx < 512; idx += 256) {
        int att = idx >> 8, r = (idx >> 4) & 15, c4 = idx & 15;
        int c = c4 * 4;
        int z = att * 2 + bb;
        float4 x = make_float4(0.f, 0.f, 0.f, 0.f);
#pragma unroll
        for (int qq = 0; qq < KS; qq++) {
            float4 y = *(const float4*)&g_pacc[(((size_t)z * KS + qq) * N + nb + r) * C + c];
            x.x += y.x; x.y += y.y; x.z += y.z; x.w += y.w;
        }
        float inv = sInv[(att * 16 + r) * 8 + (c >> 3)];
        float* dst = sA + (att * 16 + r) * 65 + c;
        dst[0] = x.x * inv; dst[1] = x.y * inv;
        dst[2] = x.z * inv; dst[3] = x.w * inv;
    }
    __syncthreads();

    int r = tid & 15, og = tid >> 4, o0 = og * 4;
    ull acc[2] = {0, 0};
    for (int k = 0; k < 64; k++) {
        float a0 = sA[(0 * 16 + r) * 65 + k];
        float a1 = sA[(1 * 16 + r) * 65 + k];
        ull pa0 = pk2(a0, a0), pa1 = pk2(a1, a1);
        const ulonglong2* w0 = (const ulonglong2*)(sW + (0 * 64 + k) * 64 + o0);
        const ulonglong2* w1 = (const ulonglong2*)(sW + (64 + k) * 64 + o0);
        ulonglong2 u0 = w0[0], u1 = w1[0];
        acc[0] = ffma2(pa0, u0.x, acc[0]); acc[1] = ffma2(pa0, u0.y, acc[1]);
        acc[0] = ffma2(pa1, u1.x, acc[0]); acc[1] = ffma2(pa1, u1.y, acc[1]);
    }

    int n = nb + r;
#pragma unroll
    for (int j = 0; j < 2; j++) {
        float lo, hi; upk2(acc[j], lo, hi);
        int o = o0 + 2 * j;
        out[((size_t)(bb * C + o)) * N + n]     = gelu_exact(lo + sB[o]);
        out[((size_t)(bb * C + o + 1)) * N + n] = gelu_exact(hi + sB[o + 1]);
    }
}

// ---------------- launch ----------------
extern "C" void kernel_launch(void* const* d_in, const int* in_sizes, int n_in,
                              void* d_out, int out_size) {
    const float* rgb    = (const float*)d_in[0];
    const float* depth  = (const float*)d_in[1];
    const float* w_exp  = (const float*)d_in[2];
    const float* b_exp  = (const float*)d_in[3];
    const float* wrq    = (const float*)d_in[4];
    const float* wrk    = (const float*)d_in[5];
    const float* wrv    = (const float*)d_in[6];
    const float* wdq    = (const float*)d_in[7];
    const float* wdk    = (const float*)d_in[8];
    const float* wdv    = (const float*)d_in[9];
    const float* wrp    = (const float*)d_in[10];
    const float* brp    = (const float*)d_in[11];
    const float* wdp    = (const float*)d_in[12];
    const float* bdp    = (const float*)d_in[13];
    const float* wcomp  = (const float*)d_in[14];
    const float* bcomp  = (const float*)d_in[15];

    const int QKV_SMEM  = (64 * 49 + 64 * 196) * 4;        // 62720
    const int ATTN_SMEM = 2 * KQ2 * 8 * 8;                 // 36864 (K+V dup pairs)
    const int OUT_SMEM  = (2080 + 8192 + 256 + 64) * 4;    // 42368

    cudaFuncSetAttribute(k_qkv,  cudaFuncAttributeMaxDynamicSharedMemorySize, QKV_SMEM);
    cudaFuncSetAttribute(k_attn, cudaFuncAttributeMaxDynamicSharedMemorySize, ATTN_SMEM);
    cudaFuncSetAttribute(k_out,  cudaFuncAttributeMaxDynamicSharedMemorySize, OUT_SMEM);

    k_weff<<<64, 128>>>(wrp, brp, wdp, bdp, wcomp, bcomp);
    k_qkv<<<dim3(48, 2, 2), 288, QKV_SMEM>>>(rgb, depth, w_exp, b_exp,
                                             wrq, wrk, wrv, wdq, wdk, wdv);
    k_attn<<<dim3(5, 64, 4), 128, ATTN_SMEM>>>();
    k_out<<<288, 256, OUT_SMEM>>>((float*)d_out);
}

// round 6
// speedup vs baseline: 1.1752x; 1.1752x over previous
#include <cuda_runtime.h>
#include <math.h>

typedef unsigned long long ull;

#define DINL __device__ __forceinline__

DINL ull pk2(float lo, float hi) {
    ull r; asm("mov.b64 %0, {%1,%2};" : "=l"(r) : "f"(lo), "f"(hi)); return r;
}
DINL void upk2(ull v, float& lo, float& hi) {
    asm("mov.b64 {%0,%1}, %2;" : "=f"(lo), "=f"(hi) : "l"(v));
}
DINL ull ffma2(ull a, ull b, ull c) {
    ull d; asm("fma.rn.f32x2 %0, %1, %2, %3;" : "=l"(d) : "l"(a), "l"(b), "l"(c)); return d;
}
DINL float ex2f(float x) {
    float y; asm("ex2.approx.f32 %0, %1;" : "=f"(y) : "f"(x)); return y;
}
DINL float gelu_exact(float x) {
    return 0.5f * x * (1.0f + erff(x * 0.7071067811865476f));
}

constexpr int B  = 2;
constexpr int C  = 64;
constexpr int HW = 48;
constexpr int N  = 2304;   // 48*48
constexpr int H  = 8;      // heads
constexpr int D  = 8;      // head dim
constexpr int KQ = 576;    // keys per quarter (key-split 4)

// ---------------- scratch (device globals; no allocs allowed) ----------------
__device__ __align__(16) float g_qkv[2][3][B * H * N * D];    // [stream][q,k,v] (b,h,n,d)
__device__ __align__(16) float g_pacc[4 * 4 * N * C];         // [z][quarter][n][c] unnormalized P·V
__device__ __align__(16) float g_psum[4 * 4 * H * N];         // [z][quarter][h][n]  sum of p
__device__ __align__(16) float g_wefft[2][C * C];             // effective weights, [att][k*64+o]
__device__ __align__(16) float g_beff[C];                     // effective bias

// ---------------- kernel 1: fused QKV GEMMs (both streams; depth path inlined) ----------------
// grid (48, 4, 2): x = w-column, y = b*2 + ocHalf, z = stream. 384 CTAs.
// Each block: 48 rows x 96 output channels.
__global__ void k_qkv(const float* __restrict__ rgb,
                      const float* __restrict__ depth,
                      const float* __restrict__ w_exp,
                      const float* __restrict__ b_exp,
                      const float* __restrict__ wq0, const float* __restrict__ wk0, const float* __restrict__ wv0,
                      const float* __restrict__ wq1, const float* __restrict__ wk1, const float* __restrict__ wv1) {
    extern __shared__ float sm[];
    float* sX  = sm;                 // [c][h] stride 49
    float* sWt = sm + 64 * 49;       // [c][oc_local] stride 100

    int w = blockIdx.x;
    int b = blockIdx.y >> 1, ocHalf = blockIdx.y & 1;
    int s = blockIdx.z;
    int tid = threadIdx.x;           // 288 threads
    int ocBase = ocHalf * 96;

    if (s == 0) {
        for (int idx = tid; idx < 64 * 48; idx += 288) {
            int c = idx / 48, h = idx % 48;
            sX[c * 49 + h] = rgb[(b * C + c) * N + h * HW + w];
        }
    } else {
        float sx = w * 0.5f - 0.25f;
        float fx = floorf(sx);
        float wx1 = sx - fx, wx0 = 1.0f - wx1;
        int x0 = max((int)fx, 0), x1 = min((int)fx + 1, 23);
        const float* dp = depth + b * 576;
        for (int idx = tid; idx < 64 * 48; idx += 288) {
            int c = idx / 48, h = idx % 48;
            float sy = h * 0.5f - 0.25f;
            float fy = floorf(sy);
            float wy1 = sy - fy, wy0 = 1.0f - wy1;
            int y0 = max((int)fy, 0), y1 = min((int)fy + 1, 23);
            float d00 = dp[y0 * 24 + x0], d01 = dp[y0 * 24 + x1];
            float d10 = dp[y1 * 24 + x0], d11 = dp[y1 * 24 + x1];
            float we = w_exp[c], be = b_exp[c];
            float v = wy0 * wx0 * fmaxf(fmaf(we, d00, be), 0.f)
                    + wy0 * wx1 * fmaxf(fmaf(we, d01, be), 0.f)
                    + wy1 * wx0 * fmaxf(fmaf(we, d10, be), 0.f)
                    + wy1 * wx1 * fmaxf(fmaf(we, d11, be), 0.f);
            sX[c * 49 + h] = v;
        }
    }
    const float* wq = s ? wq1 : wq0;
    const float* wk = s ? wk1 : wk0;
    const float* wv = s ? wv1 : wv0;
    for (int idx = tid; idx < 64 * 96; idx += 288) {
        int ocl = idx / 64, c = idx % 64;
        int oc = ocBase + ocl;
        int sel = oc >> 6, ocm = oc & 63;
        const float* wm = (sel == 0) ? wq : (sel == 1 ? wk : wv);
        sWt[c * 100 + ocl] = wm[ocm * 64 + c];
    }
    __syncthreads();

    int nl = tid % 48;        // = h (row)
    int g  = tid / 48;        // 0..5
    int oc0 = g * 16;         // local oc start (16 channels per thread)

    ull acc[8];
#pragma unroll
    for (int j = 0; j < 8; j++) acc[j] = 0ull;

    for (int c = 0; c < 64; c++) {
        float xv = sX[c * 49 + nl];
        ull xp = pk2(xv, xv);
        const ulonglong2* w2 = (const ulonglong2*)(sWt + c * 100 + oc0);
#pragma unroll
        for (int j = 0; j < 4; j++) {
            ulonglong2 wv2 = w2[j];
            acc[2 * j]     = ffma2(xp, wv2.x, acc[2 * j]);
            acc[2 * j + 1] = ffma2(xp, wv2.y, acc[2 * j + 1]);
        }
    }

    int n = w * HW + nl;
#pragma unroll
    for (int j = 0; j < 8; j++) {
        int oc = ocBase + oc0 + 2 * j;
        int mat = oc >> 6, ocm = oc & 63, hd = ocm >> 3, d = ocm & 7;
        float lo, hi; upk2(acc[j], lo, hi);
        *(float2*)&g_qkv[s][mat][((size_t)(b * H + hd) * N + n) * D + d] = make_float2(lo, hi);
    }
}

// ---------------- kernel 2: cross-attention (R4 structure + packed-ss) ----------------
// key-split 4 (576 keys/quarter, smem 36.9KB), 128-thread CTAs, 6 CTA/SM,
// 2 queries/thread, pair-interleaved K (one ffma2 = 2 key logits).
// grid: x = q-chunk (9, 256 q each), y = h + 8*quarter (32), z = att*2 + b (4). 1152 blocks.
__global__ void __launch_bounds__(128, 6) k_attn() {
    extern __shared__ float sm[];
    ull*    sK = (ull*)sm;                    // 288 pairs * 8 ull = 18432 B
    float4* sV = (float4*)(sm + 4608);        // 576 keys * 2 float4 = 18432 B

    int chunk = blockIdx.x;
    int h = blockIdx.y & 7, quarter = blockIdx.y >> 3;
    int z = blockIdx.z;                        // att*2+b
    int att = z >> 1, b = z & 1;
    int tid = threadIdx.x;

    const float* Kg = g_qkv[1 - att][1] + ((size_t)(b * H + h) * N + quarter * KQ) * D;
    const float* Vg = g_qkv[1 - att][2] + ((size_t)(b * H + h) * N + quarter * KQ) * D;

    const float4* Vg4 = (const float4*)Vg;
    for (int i = tid; i < KQ * 2; i += 128) sV[i] = Vg4[i];
    const float4* Kg4 = (const float4*)Kg;
    for (int j = tid; j < KQ / 2; j += 128) {
        float4 a0 = Kg4[4 * j], a1 = Kg4[4 * j + 1];
        float4 c0 = Kg4[4 * j + 2], c1 = Kg4[4 * j + 3];
        ull* d = sK + j * 8;
        d[0] = pk2(a0.x, c0.x); d[1] = pk2(a0.y, c0.y);
        d[2] = pk2(a0.z, c0.z); d[3] = pk2(a0.w, c0.w);
        d[4] = pk2(a1.x, c1.x); d[5] = pk2(a1.y, c1.y);
        d[6] = pk2(a1.z, c1.z); d[7] = pk2(a1.w, c1.w);
    }
    __syncthreads();

    int n0 = chunk * 256 + tid;
    int n1 = n0 + 128;
    const float* Qb = g_qkv[att][0] + (size_t)(b * H + h) * N * D;

    constexpr float QS = 0.3535533905932738f * 1.4426950408889634f; // scale * log2(e)
    constexpr float SHIFTF = -14.4269504088896f;                     // cancels in normalization

    float4 qa = *(const float4*)(Qb + (size_t)n0 * D);
    float4 qb = *(const float4*)(Qb + (size_t)n0 * D + 4);
    float4 qc = *(const float4*)(Qb + (size_t)n1 * D);
    float4 qd = *(const float4*)(Qb + (size_t)n1 * D + 4);
    ull qp0[8], qp1[8];
    qp0[0] = pk2(qa.x * QS, qa.x * QS); qp0[1] = pk2(qa.y * QS, qa.y * QS);
    qp0[2] = pk2(qa.z * QS, qa.z * QS); qp0[3] = pk2(qa.w * QS, qa.w * QS);
    qp0[4] = pk2(qb.x * QS, qb.x * QS); qp0[5] = pk2(qb.y * QS, qb.y * QS);
    qp0[6] = pk2(qb.z * QS, qb.z * QS); qp0[7] = pk2(qb.w * QS, qb.w * QS);
    qp1[0] = pk2(qc.x * QS, qc.x * QS); qp1[1] = pk2(qc.y * QS, qc.y * QS);
    qp1[2] = pk2(qc.z * QS, qc.z * QS); qp1[3] = pk2(qc.w * QS, qc.w * QS);
    qp1[4] = pk2(qd.x * QS, qd.x * QS); qp1[5] = pk2(qd.y * QS, qd.y * QS);
    qp1[6] = pk2(qd.z * QS, qd.z * QS); qp1[7] = pk2(qd.w * QS, qd.w * QS);

    const ull SH2  = pk2(SHIFTF, SHIFTF);
    const ull ONE2 = pk2(1.0f, 1.0f);
    const ulonglong2* sK2 = (const ulonglong2*)sK;
    const ulonglong2* sV2 = (const ulonglong2*)sV;

    ull acc0[4] = {0, 0, 0, 0}, acc1[4] = {0, 0, 0, 0};
    ull ssp0 = 0ull, ssp1 = 0ull;   // packed partial sums (even-key lane, odd-key lane)

#pragma unroll 2
    for (int j = 0; j < KQ / 2; j++) {
        ulonglong2 kA = sK2[4 * j],     kB = sK2[4 * j + 1];
        ulonglong2 kC = sK2[4 * j + 2], kD = sK2[4 * j + 3];
        ull t0 = ffma2(qp0[0], kA.x, SH2);
        ull t1 = ffma2(qp1[0], kA.x, SH2);
        t0 = ffma2(qp0[1], kA.y, t0); t1 = ffma2(qp1[1], kA.y, t1);
        t0 = ffma2(qp0[2], kB.x, t0); t1 = ffma2(qp1[2], kB.x, t1);
        t0 = ffma2(qp0[3], kB.y, t0); t1 = ffma2(qp1[3], kB.y, t1);
        t0 = ffma2(qp0[4], kC.x, t0); t1 = ffma2(qp1[4], kC.x, t1);
        t0 = ffma2(qp0[5], kC.y, t0); t1 = ffma2(qp1[5], kC.y, t1);
        t0 = ffma2(qp0[6], kD.x, t0); t1 = ffma2(qp1[6], kD.x, t1);
        t0 = ffma2(qp0[7], kD.y, t0); t1 = ffma2(qp1[7], kD.y, t1);

        float s00, s01, s10, s11;
        upk2(t0, s00, s01); upk2(t1, s10, s11);
        float p00 = ex2f(s00), p01 = ex2f(s01);
        float p10 = ex2f(s10), p11 = ex2f(s11);
        ssp0 = ffma2(pk2(p00, p01), ONE2, ssp0);
        ssp1 = ffma2(pk2(p10, p11), ONE2, ssp1);
        ull pp00 = pk2(p00, p00), pp01 = pk2(p01, p01);
        ull pp10 = pk2(p10, p10), pp11 = pk2(p11, p11);

        ulonglong2 vA = sV2[4 * j],     vB = sV2[4 * j + 1];  // key 2j   d0-7
        ulonglong2 vC = sV2[4 * j + 2], vD = sV2[4 * j + 3];  // key 2j+1 d0-7
        acc0[0] = ffma2(pp00, vA.x, acc0[0]); acc0[1] = ffma2(pp00, vA.y, acc0[1]);
        acc0[2] = ffma2(pp00, vB.x, acc0[2]); acc0[3] = ffma2(pp00, vB.y, acc0[3]);
        acc0[0] = ffma2(pp01, vC.x, acc0[0]); acc0[1] = ffma2(pp01, vC.y, acc0[1]);
        acc0[2] = ffma2(pp01, vD.x, acc0[2]); acc0[3] = ffma2(pp01, vD.y, acc0[3]);
        acc1[0] = ffma2(pp10, vA.x, acc1[0]); acc1[1] = ffma2(pp10, vA.y, acc1[1]);
        acc1[2] = ffma2(pp10, vB.x, acc1[2]); acc1[3] = ffma2(pp10, vB.y, acc1[3]);
        acc1[0] = ffma2(pp11, vC.x, acc1[0]); acc1[1] = ffma2(pp11, vC.y, acc1[1]);
        acc1[2] = ffma2(pp11, vD.x, acc1[2]); acc1[3] = ffma2(pp11, vD.y, acc1[3]);
    }

    float se0, so0, se1, so1;
    upk2(ssp0, se0, so0);
    upk2(ssp1, se1, so1);

    // store unnormalized partials (combined linearly in k_out)
    size_t pb0 = (((size_t)z * 4 + quarter) * N + n0) * C + h * D;
    size_t pb1 = (((size_t)z * 4 + quarter) * N + n1) * C + h * D;
    float4 f;
    upk2(acc0[0], f.x, f.y); upk2(acc0[1], f.z, f.w); *(float4*)&g_pacc[pb0]     = f;
    upk2(acc0[2], f.x, f.y); upk2(acc0[3], f.z, f.w); *(float4*)&g_pacc[pb0 + 4] = f;
    upk2(acc1[0], f.x, f.y); upk2(acc1[1], f.z, f.w); *(float4*)&g_pacc[pb1]     = f;
    upk2(acc1[2], f.x, f.y); upk2(acc1[3], f.z, f.w); *(float4*)&g_pacc[pb1 + 4] = f;
    size_t sb = (((size_t)z * 4 + quarter) * H + h) * N;
    g_psum[sb + n0] = se0 + so0;
    g_psum[sb + n1] = se1 + so1;
}

// ---------------- kernel 3: effective proj+compress weights ----------------
__global__ void k_weff(const float* __restrict__ wrp, const float* __restrict__ brp,
                       const float* __restrict__ wdp, const float* __restrict__ bdp,
                       const float* __restrict__ wcomp, const float* __restrict__ bcomp) {
    __shared__ float sWc[128];
    __shared__ float sRed[64];
    int o = blockIdx.x;
    int tid = threadIdx.x;   // 128
    sWc[tid] = wcomp[o * 128 + tid];
    __syncthreads();
    int att = tid >> 6, k = tid & 63;
    const float* wp = att ? wdp : wrp;
    float acc = 0.f;
#pragma unroll
    for (int c = 0; c < 64; c++)
        acc = fmaf(sWc[att * 64 + c], wp[c * 64 + k], acc);
    g_wefft[att][k * 64 + o] = acc;
    if (tid < 64) sRed[tid] = sWc[tid] * brp[tid] + sWc[64 + tid] * bdp[tid];
    __syncthreads();
    if (tid == 0) {
        float a = bcomp[o];
        for (int c = 0; c < 64; c++) a += sRed[c];
        g_beff[o] = a;
    }
}

// ---------------- kernel 4: combine partials + (proj+compress) GEMM + GELU ----------------
// 288 blocks x 16 rows, 256 threads
__global__ void k_out(float* __restrict__ out) {
    extern __shared__ float sm[];
    float* sA   = sm;            // [att][r][k] stride 65 -> 2080 floats
    float* sW   = sm + 2080;     // [att][k][o]          -> 8192 floats
    float* sInv = sm + 10272;    // [att][r][h]          -> 256 floats
    float* sB   = sm + 10528;    // 64 floats

    int tid = threadIdx.x;
    int row0 = blockIdx.x * 16;
    int bb = row0 / N;
    int nb = row0 - bb * N;

    // 1/(sum over 4 quarters of psum)
    if (tid < 256) {
        int idx = tid;
        int att = idx >> 7, r = (idx >> 3) & 15, hh = idx & 7;
        int n = nb + r;
        int z = att * 2 + bb;
        float s = 0.f;
#pragma unroll
        for (int qq = 0; qq < 4; qq++)
            s += g_psum[(((size_t)z * 4 + qq) * H + hh) * N + n];
        sInv[(att * 16 + r) * 8 + hh] = 1.0f / s;
    }
    for (int idx = tid; idx < 2 * 64 * 64; idx += 256)
        sW[idx] = ((const float*)g_wefft)[idx];
    if (tid < 64) sB[tid] = g_beff[tid];
    __syncthreads();

    // combine pacc quarters, normalize -> sA
    for (int idx = tid; idx < 512; idx += 256) {
        int att = idx >> 8, r = (idx >> 4) & 15, c4 = idx & 15;
        int c = c4 * 4;
        int z = att * 2 + bb;
        float4 x = make_float4(0.f, 0.f, 0.f, 0.f);
#pragma unroll
        for (int qq = 0; qq < 4; qq++) {
            float4 y = *(const float4*)&g_pacc[(((size_t)z * 4 + qq) * N + nb + r) * C + c];
            x.x += y.x; x.y += y.y; x.z += y.z; x.w += y.w;
        }
        float inv = sInv[(att * 16 + r) * 8 + (c >> 3)];
        float* dst = sA + (att * 16 + r) * 65 + c;
        dst[0] = x.x * inv; dst[1] = x.y * inv;
        dst[2] = x.z * inv; dst[3] = x.w * inv;
    }
    __syncthreads();

    int r = tid & 15, og = tid >> 4, o0 = og * 4;
    ull acc[2] = {0, 0};
    for (int k = 0; k < 64; k++) {
        float a0 = sA[(0 * 16 + r) * 65 + k];
        float a1 = sA[(1 * 16 + r) * 65 + k];
        ull pa0 = pk2(a0, a0), pa1 = pk2(a1, a1);
        const ulonglong2* w0 = (const ulonglong2*)(sW + (0 * 64 + k) * 64 + o0);
        const ulonglong2* w1 = (const ulonglong2*)(sW + (64 + k) * 64 + o0);
        ulonglong2 u0 = w0[0], u1 = w1[0];
        acc[0] = ffma2(pa0, u0.x, acc[0]); acc[1] = ffma2(pa0, u0.y, acc[1]);
        acc[0] = ffma2(pa1, u1.x, acc[0]); acc[1] = ffma2(pa1, u1.y, acc[1]);
    }

    int n = nb + r;
#pragma unroll
    for (int j = 0; j < 2; j++) {
        float lo, hi; upk2(acc[j], lo, hi);
        int o = o0 + 2 * j;
        out[((size_t)(bb * C + o)) * N + n]     = gelu_exact(lo + sB[o]);
        out[((size_t)(bb * C + o + 1)) * N + n] = gelu_exact(hi + sB[o + 1]);
    }
}

// ---------------- launch ----------------
extern "C" void kernel_launch(void* const* d_in, const int* in_sizes, int n_in,
                              void* d_out, int out_size) {
    const float* rgb    = (const float*)d_in[0];
    const float* depth  = (const float*)d_in[1];
    const float* w_exp  = (const float*)d_in[2];
    const float* b_exp  = (const float*)d_in[3];
    const float* wrq    = (const float*)d_in[4];
    const float* wrk    = (const float*)d_in[5];
    const float* wrv    = (const float*)d_in[6];
    const float* wdq    = (const float*)d_in[7];
    const float* wdk    = (const float*)d_in[8];
    const float* wdv    = (const float*)d_in[9];
    const float* wrp    = (const float*)d_in[10];
    const float* brp    = (const float*)d_in[11];
    const float* wdp    = (const float*)d_in[12];
    const float* bdp    = (const float*)d_in[13];
    const float* wcomp  = (const float*)d_in[14];
    const float* bcomp  = (const float*)d_in[15];

    const int QKV_SMEM  = (64 * 49 + 64 * 100) * 4;        // 38144
    const int ATTN_SMEM = 2 * KQ * D * 4;                  // 36864
    const int OUT_SMEM  = (2080 + 8192 + 256 + 64) * 4;    // 42368

    cudaFuncSetAttribute(k_qkv,  cudaFuncAttributeMaxDynamicSharedMemorySize, QKV_SMEM);
    cudaFuncSetAttribute(k_attn, cudaFuncAttributeMaxDynamicSharedMemorySize, ATTN_SMEM);
    cudaFuncSetAttribute(k_out,  cudaFuncAttributeMaxDynamicSharedMemorySize, OUT_SMEM);

    k_weff<<<64, 128>>>(wrp, brp, wdp, bdp, wcomp, bcomp);
    k_qkv<<<dim3(48, 4, 2), 288, QKV_SMEM>>>(rgb, depth, w_exp, b_exp,
                                             wrq, wrk, wrv, wdq, wdk, wdv);
    k_attn<<<dim3(9, 32, 4), 128, ATTN_SMEM>>>();
    k_out<<<288, 256, OUT_SMEM>>>((float*)d_out);
}